// round 10
// baseline (speedup 1.0000x reference)
#include <cuda_runtime.h>

// rate_RNN_mante: T=1000, B=64, I=4, H=1024, O=2, P=16
// Low-rank recurrence: r @ Wr^T = (r @ pout) @ (l*pin)^T
// One persistent CTA per batch element; mem state in registers.
// R10 = R9 + smem zz broadcast (replaces 16-SHFL in-warp broadcast with
//       parity-double-buffered duplicated-pair smem row; benign identical
//       cross-warp writes), minor chain trims.

#define T_STEPS 1000
#define BATCH   64
#define I_DIM   4
#define H_DIM   1024
#define O_DIM   2
#define P_DIM   16
#define HPT     4                 // h-rows per thread
#define NTHREADS 256              // H_DIM / HPT
#define NWARPS  (NTHREADS / 32)
#define NRED    18                // 16 z-values + 2 y-values
#define NRED2   9
#define PROW    34                // 32 z-partial cols + 2 y cols (8B-aligned rows)

typedef unsigned long long u64;

__device__ __forceinline__ float fast_tanh(float x) {
    float r;
    asm("tanh.approx.f32 %0, %1;" : "=f"(r) : "f"(x));
    return r;
}
__device__ __forceinline__ float shfl_xor_f(float v, int off) {
    return __shfl_xor_sync(0xffffffffu, v, off);
}
__device__ __forceinline__ u64 pk2(float lo, float hi) {
    u64 r; asm("mov.b64 %0, {%1, %2};" : "=l"(r) : "f"(lo), "f"(hi)); return r;
}
__device__ __forceinline__ void upk2(u64 v, float& lo, float& hi) {
    asm("mov.b64 {%0, %1}, %2;" : "=f"(lo), "=f"(hi) : "l"(v));
}
__device__ __forceinline__ u64 fma2(u64 a, u64 b, u64 c) {
    u64 d; asm("fma.rn.f32x2 %0, %1, %2, %3;" : "=l"(d) : "l"(a), "l"(b), "l"(c)); return d;
}
__device__ __forceinline__ u64 add2(u64 a, u64 b) {
    u64 d; asm("add.rn.f32x2 %0, %1, %2;" : "=l"(d) : "l"(a), "l"(b)); return d;
}
__device__ __forceinline__ u64 mul2(u64 a, u64 b) {
    u64 d; asm("mul.rn.f32x2 %0, %1, %2;" : "=l"(d) : "l"(a), "l"(b)); return d;
}

__global__ __launch_bounds__(NTHREADS, 1)
void rate_rnn_kernel(const float* __restrict__ x,     // (T,B,I,1)
                     const float* __restrict__ Win,   // (H,I)
                     const float* __restrict__ Wout,  // (O,H)
                     const float* __restrict__ pin,   // (H,P)
                     const float* __restrict__ pout,  // (H,P)
                     const float* __restrict__ l,     // (P,)
                     float* __restrict__ y)           // (T,B,O,1)
{
    const int b    = blockIdx.x;
    const int tid  = threadIdx.x;
    const int lane = tid & 31;
    const int warp = tid >> 5;

    // double-buffered per-warp partials: [parity][warp][32 z-partials | 2 y]
    __shared__ __align__(16) float pbuf[2][NWARPS][PROW];
    // double-buffered duplicated z pairs: [parity][16] of (z,z)
    __shared__ __align__(16) u64 zzbuf[2][P_DIM];

    const float lm = 0.95122942450071400910f;  // exp(-DT/TAUM) = exp(-0.05)
    const float om = 1.0f - lm;
    const u64 lm2  = pk2(lm, lm);

    // butterfly lane roles
    const bool hi16 = (lane & 16) != 0;
    const bool hi8  = (lane & 8)  != 0;
    const bool hi4  = (lane & 4)  != 0;
    const bool hi2  = (lane & 2)  != 0;
    const bool wy   = (lane & 15) == 0;           // y writer lanes (0 and 16)
    const int  ycol = 32 + (lane >> 4);           // y column in pbuf row

    // ---- setup: scalar staging, then pack ----
    float lvec[P_DIM];
    #pragma unroll
    for (int p = 0; p < P_DIM; p++) lvec[p] = l[p];

    float msc[HPT][NRED];      // [pout(16) | Wout^T(2)]
    float wsc[HPT][I_DIM];     // om * Win
    float lsc[HPT][P_DIM];     // om * l * pin
    #pragma unroll
    for (int k = 0; k < HPT; k++) {
        const int h = tid + k * NTHREADS;
        #pragma unroll
        for (int i = 0; i < I_DIM; i++) wsc[k][i] = om * Win[h * I_DIM + i];
        #pragma unroll
        for (int p = 0; p < P_DIM; p++) {
            msc[k][p] = pout[h * P_DIM + p];
            lsc[k][p] = om * lvec[p] * pin[h * P_DIM + p];
        }
        msc[k][16] = Wout[h];
        msc[k][17] = Wout[H_DIM + h];
    }

    u64 m2[HPT][NRED2];        // packed along j (phase 1)
    #pragma unroll
    for (int k = 0; k < HPT; k++)
        #pragma unroll
        for (int j = 0; j < NRED2; j++)
            m2[k][j] = pk2(msc[k][2 * j], msc[k][2 * j + 1]);

    u64 win2[2][I_DIM];        // packed along k-pairs (phase 3)
    u64 lp2[2][P_DIM];
    #pragma unroll
    for (int c = 0; c < 2; c++) {
        #pragma unroll
        for (int i = 0; i < I_DIM; i++) win2[c][i] = pk2(wsc[2 * c][i], wsc[2 * c + 1][i]);
        #pragma unroll
        for (int p = 0; p < P_DIM; p++) lp2[c][p]  = pk2(lsc[2 * c][p], lsc[2 * c + 1][p]);
    }

    u64 mem2[2] = {0ull, 0ull};   // (mem_k0,mem_k1), (mem_k2,mem_k3)

    const float4* xp = reinterpret_cast<const float4*>(x) + b;
    float4 xc = __ldg(xp);   // t = 0
    float4 xn = xc;

    // Iteration t: r_t = tanh(mem_t); y[t-1] = Wout.r_t; advance mem (t < T).
    for (int t = 0; t <= T_STEPS; t++) {
        {   // clamped prefetch of next x
            int tn = t + 1; if (tn > T_STEPS - 1) tn = T_STEPS - 1;
            xn = __ldg(xp + tn * BATCH);
        }
        float (*pb)[PROW] = pbuf[t & 1];

        // ---- phase 1: tanh + packed accumulation ----
        float mk[HPT];
        upk2(mem2[0], mk[0], mk[1]);
        upk2(mem2[1], mk[2], mk[3]);

        u64 part2[NRED2];
        #pragma unroll
        for (int j = 0; j < NRED2; j++) part2[j] = 0ull;

        #pragma unroll
        for (int k = 0; k < HPT; k++) {
            const float r = fast_tanh(mk[k]);
            const u64 rr = pk2(r, r);
            #pragma unroll
            for (int j = 0; j < NRED2; j++)
                part2[j] = fma2(rr, m2[k][j], part2[j]);
        }
        float part[NRED];
        #pragma unroll
        for (int j = 0; j < NRED2; j++) upk2(part2[j], part[2 * j], part[2 * j + 1]);

        // ---- z-independent drive, hoisted & packed ----
        u64 xx[I_DIM];
        xx[0] = pk2(xc.x, xc.x);
        xx[1] = pk2(xc.y, xc.y);
        xx[2] = pk2(xc.z, xc.z);
        xx[3] = pk2(xc.w, xc.w);
        u64 a0p[2];
        #pragma unroll
        for (int c = 0; c < 2; c++) {
            u64 a = mul2(lm2, mem2[c]);
            #pragma unroll
            for (int i = 0; i < I_DIM; i++)
                a = fma2(win2[c][i], xx[i], a);
            a0p[c] = a;
        }

        // ---- split-butterfly: rounds 16/8/4/2 (no final xor-1) ----
        float v8[8];
        #pragma unroll
        for (int i = 0; i < 8; i++) {
            float send = hi16 ? part[i] : part[i + 8];
            float keep = hi16 ? part[i + 8] : part[i];
            v8[i] = keep + shfl_xor_f(send, 16);
        }
        float v4[4];
        #pragma unroll
        for (int i = 0; i < 4; i++) {
            float send = hi8 ? v8[i] : v8[i + 4];
            float keep = hi8 ? v8[i + 4] : v8[i];
            v4[i] = keep + shfl_xor_f(send, 8);
        }
        float v2[2];
        #pragma unroll
        for (int i = 0; i < 2; i++) {
            float send = hi4 ? v4[i] : v4[i + 2];
            float keep = hi4 ? v4[i + 2] : v4[i];
            v2[i] = keep + shfl_xor_f(send, 4);
        }
        float v1;
        {
            float send = hi2 ? v2[0] : v2[1];
            float keep = hi2 ? v2[1] : v2[0];
            v1 = keep + shfl_xor_f(send, 2);
        }
        // lane L holds one of two partials of z[(L>>1)&15]

        // ---- y: split once, then 4 naive rounds ----
        float wv;
        {
            float send = hi16 ? part[16] : part[17];
            float keep = hi16 ? part[17] : part[16];
            wv = keep + shfl_xor_f(send, 16);
        }
        wv += shfl_xor_f(wv, 8);
        wv += shfl_xor_f(wv, 4);
        wv += shfl_xor_f(wv, 2);
        wv += shfl_xor_f(wv, 1);

        pb[warp][lane] = v1;          // coalesced, no predicate
        if (wy) pb[warp][ycol] = wv;  // lanes 0 (y0) and 16 (y1)
        __syncthreads();              // the ONLY block barrier per step

        // ---- redundant per-warp cross-warp reduce (lanes 0..16), packed ----
        float sx = 0.0f, sy = 0.0f;
        if (lane < 17) {
            const int c = 2 * lane;   // lane 16 -> cols 32,33 = (y0,y1)
            u64 q0 = *reinterpret_cast<const u64*>(&pb[0][c]);
            u64 q1 = *reinterpret_cast<const u64*>(&pb[1][c]);
            u64 q2 = *reinterpret_cast<const u64*>(&pb[2][c]);
            u64 q3 = *reinterpret_cast<const u64*>(&pb[3][c]);
            u64 q4 = *reinterpret_cast<const u64*>(&pb[4][c]);
            u64 q5 = *reinterpret_cast<const u64*>(&pb[5][c]);
            u64 q6 = *reinterpret_cast<const u64*>(&pb[6][c]);
            u64 q7 = *reinterpret_cast<const u64*>(&pb[7][c]);
            u64 s = add2(add2(add2(q0, q1), add2(q2, q3)),
                         add2(add2(q4, q5), add2(q6, q7)));
            upk2(s, sx, sy);
        }
        const float zval = sx + sy;   // lanes 0..15: z[lane]

        // y store: lane 16 of warp 0 holds (y_o0, y_o1) in (sx, sy)
        if (warp == 0 && lane == 16 && t > 0) {
            *reinterpret_cast<float2*>(&y[((t - 1) * BATCH + b) * O_DIM]) =
                make_float2(sx, sy);
        }

        if (t == T_STEPS) break;

        // ---- publish z as duplicated (z,z) pairs to smem; warps write
        //      bitwise-identical values (same inputs, same op order) so the
        //      cross-warp overlap is benign; parity buffer gives 2-barrier
        //      separation before reuse ----
        u64* zzb = zzbuf[t & 1];
        if (lane < P_DIM) zzb[lane] = pk2(zval, zval);
        __syncwarp();

        u64 zz[P_DIM];
        {
            const ulonglong2* zv = reinterpret_cast<const ulonglong2*>(zzb);
            #pragma unroll
            for (int q = 0; q < 8; q++) {
                ulonglong2 v = zv[q];      // broadcast LDS.128
                zz[2 * q]     = v.x;
                zz[2 * q + 1] = v.y;
            }
        }

        // ---- phase 3: packed z feedback + hoisted drive ----
        #pragma unroll
        for (int c = 0; c < 2; c++) {
            u64 a1 = mul2(zz[0], lp2[c][0]);
            #pragma unroll
            for (int p = 1; p < 8; p++)
                a1 = fma2(zz[p], lp2[c][p], a1);

            u64 a2 = mul2(zz[8], lp2[c][8]);
            #pragma unroll
            for (int p = 9; p < 16; p++)
                a2 = fma2(zz[p], lp2[c][p], a2);

            mem2[c] = add2(a0p[c], add2(a1, a2));
        }
        xc = xn;
    }
}

extern "C" void kernel_launch(void* const* d_in, const int* in_sizes, int n_in,
                              void* d_out, int out_size)
{
    const float* x    = (const float*)d_in[0];
    const float* Win  = (const float*)d_in[1];
    const float* Wout = (const float*)d_in[2];
    const float* pin  = (const float*)d_in[3];
    const float* pout = (const float*)d_in[4];
    const float* l    = (const float*)d_in[5];
    float* y = (float*)d_out;

    rate_rnn_kernel<<<BATCH, NTHREADS>>>(x, Win, Wout, pin, pout, l, y);
}

// round 11
// speedup vs baseline: 1.0686x; 1.0686x over previous
#include <cuda_runtime.h>

// rate_RNN_mante: T=1000, B=64, I=4, H=1024, O=2, P=16
// Low-rank recurrence: r @ Wr^T = (r @ pout) @ (l*pin)^T
// One persistent CTA per batch element; mem state in registers.
// R11 = R5 (best measured: scalar, 2 barriers, 5-round split butterfly,
//       smem zbuf broadcast) + ONE delta: z-independent drive hoisted
//       before bar1 (om folded into win/lp), shortening the post-bar2 chain.

#define T_STEPS 1000
#define BATCH   64
#define I_DIM   4
#define H_DIM   1024
#define O_DIM   2
#define P_DIM   16
#define HPT     4                 // h-rows per thread
#define NTHREADS 256              // H_DIM / HPT
#define NWARPS  (NTHREADS / 32)
#define NRED    18                // 16 z-values + 2 y-values
#define PROW    20                // pbuf row stride (floats), conflict-free columns

__device__ __forceinline__ float fast_tanh(float x) {
    float r;
    asm("tanh.approx.f32 %0, %1;" : "=f"(r) : "f"(x));
    return r;
}
__device__ __forceinline__ float shfl_xor_f(float v, int off) {
    return __shfl_xor_sync(0xffffffffu, v, off);
}

__global__ __launch_bounds__(NTHREADS, 1)
void rate_rnn_kernel(const float* __restrict__ x,     // (T,B,I,1)
                     const float* __restrict__ Win,   // (H,I)
                     const float* __restrict__ Wout,  // (O,H)
                     const float* __restrict__ pin,   // (H,P)
                     const float* __restrict__ pout,  // (H,P)
                     const float* __restrict__ l,     // (P,)
                     float* __restrict__ y)           // (T,B,O,1)
{
    const int b    = blockIdx.x;
    const int tid  = threadIdx.x;
    const int lane = tid & 31;
    const int warp = tid >> 5;

    __shared__ __align__(16) float pbuf[NWARPS][PROW];  // per-warp reduced values
    __shared__ __align__(16) float zbuf[P_DIM];         // broadcast z

    const float lm = 0.95122942450071400910f;  // exp(-DT/TAUM) = exp(-0.05)
    const float om = 1.0f - lm;

    // split-butterfly lane roles
    const bool hi16 = (lane & 16) != 0;
    const bool hi8  = (lane & 8)  != 0;
    const bool hi4  = (lane & 4)  != 0;
    const bool hi2  = (lane & 2)  != 0;
    const bool wz   = (lane & 1)  == 0;           // z writer lanes
    const int  zj   = (lane >> 1) & 15;           // z index this lane-pair owns
    const bool wy   = (lane & 15) == 0;           // y writer lanes (0 and 16)
    const int  yj   = 16 + (lane >> 4);           // y index

    float lvec[P_DIM];
    #pragma unroll
    for (int p = 0; p < P_DIM; p++) lvec[p] = l[p];

    float mem[HPT];
    float win[HPT][I_DIM];     // om * Win (folded)
    float m[HPT][NRED];        // [pout (16) | Wout^T (2)]
    float lp[HPT][P_DIM];      // om * l * pin (folded)

    #pragma unroll
    for (int k = 0; k < HPT; k++) {
        const int h = tid + k * NTHREADS;
        mem[k] = 0.0f;
        #pragma unroll
        for (int i = 0; i < I_DIM; i++) win[k][i] = om * Win[h * I_DIM + i];
        #pragma unroll
        for (int p = 0; p < P_DIM; p++) {
            m[k][p]  = pout[h * P_DIM + p];
            lp[k][p] = om * lvec[p] * pin[h * P_DIM + p];
        }
        m[k][16] = Wout[h];           // Wout[0][h]
        m[k][17] = Wout[H_DIM + h];   // Wout[1][h]
    }

    const float4* xp = reinterpret_cast<const float4*>(x) + b;
    float4 xc = __ldg(xp);   // t = 0
    float4 xn = xc;

    // Iteration t: r_t = tanh(mem_t); y[t-1] = Wout.r_t; advance mem (t < T).
    for (int t = 0; t <= T_STEPS; t++) {
        {   // clamped prefetch of next x
            int tn = t + 1; if (tn > T_STEPS - 1) tn = T_STEPS - 1;
            xn = __ldg(xp + tn * BATCH);
        }

        // ---- phase 1: tanh + local accumulation ----
        float part[NRED];
        #pragma unroll
        for (int j = 0; j < NRED; j++) part[j] = 0.0f;

        #pragma unroll
        for (int k = 0; k < HPT; k++) {
            const float r = fast_tanh(mem[k]);
            #pragma unroll
            for (int j = 0; j < NRED; j++)
                part[j] = fmaf(r, m[k][j], part[j]);
        }

        // ---- z-independent drive, hoisted off the post-bar2 chain ----
        float a0r[HPT];
        #pragma unroll
        for (int k = 0; k < HPT; k++) {
            float a = lm * mem[k];
            a = fmaf(win[k][0], xc.x, a);
            a = fmaf(win[k][1], xc.y, a);
            a = fmaf(win[k][2], xc.z, a);
            a = fmaf(win[k][3], xc.w, a);
            a0r[k] = a;
        }

        // ---- split-butterfly: 16 z values, halving live set each round ----
        float v8[8];
        #pragma unroll
        for (int i = 0; i < 8; i++) {
            float send = hi16 ? part[i] : part[i + 8];
            float keep = hi16 ? part[i + 8] : part[i];
            v8[i] = keep + shfl_xor_f(send, 16);
        }
        float v4[4];
        #pragma unroll
        for (int i = 0; i < 4; i++) {
            float send = hi8 ? v8[i] : v8[i + 4];
            float keep = hi8 ? v8[i + 4] : v8[i];
            v4[i] = keep + shfl_xor_f(send, 8);
        }
        float v2[2];
        #pragma unroll
        for (int i = 0; i < 2; i++) {
            float send = hi4 ? v4[i] : v4[i + 2];
            float keep = hi4 ? v4[i + 2] : v4[i];
            v2[i] = keep + shfl_xor_f(send, 4);
        }
        float v1;
        {
            float send = hi2 ? v2[0] : v2[1];
            float keep = hi2 ? v2[1] : v2[0];
            v1 = keep + shfl_xor_f(send, 2);
        }
        v1 += shfl_xor_f(v1, 1);   // lane pair holds z[zj]

        // ---- y values: split once (16), then naive 4 rounds ----
        float wv;
        {
            float send = hi16 ? part[16] : part[17];
            float keep = hi16 ? part[17] : part[16];
            wv = keep + shfl_xor_f(send, 16);
        }
        wv += shfl_xor_f(wv, 8);
        wv += shfl_xor_f(wv, 4);
        wv += shfl_xor_f(wv, 2);
        wv += shfl_xor_f(wv, 1);

        if (wz) pbuf[warp][zj] = v1;
        if (wy) pbuf[warp][yj] = wv;
        __syncthreads();

        // ---- phase 2: cross-warp reduce; z -> smem, y -> global ----
        if (tid < NRED) {
            float s = pbuf[0][tid];
            #pragma unroll
            for (int w = 1; w < NWARPS; w++) s += pbuf[w][tid];
            if (tid < P_DIM) {
                zbuf[tid] = s;
            } else if (t > 0) {
                y[((t - 1) * BATCH + b) * O_DIM + (tid - P_DIM)] = s;
            }
        }
        __syncthreads();

        if (t == T_STEPS) break;

        // ---- phase 3: z feedback only (drive already in a0r) ----
        const float4* zv = reinterpret_cast<const float4*>(zbuf);
        const float4 z0 = zv[0], z1 = zv[1], z2 = zv[2], z3 = zv[3];

        #pragma unroll
        for (int k = 0; k < HPT; k++) {
            float a1 = z0.x * lp[k][0];
            a1 = fmaf(z0.y, lp[k][1],  a1);
            a1 = fmaf(z0.z, lp[k][2],  a1);
            a1 = fmaf(z0.w, lp[k][3],  a1);
            a1 = fmaf(z1.x, lp[k][4],  a1);
            a1 = fmaf(z1.y, lp[k][5],  a1);
            a1 = fmaf(z1.z, lp[k][6],  a1);
            a1 = fmaf(z1.w, lp[k][7],  a1);

            float a2 = z2.x * lp[k][8];
            a2 = fmaf(z2.y, lp[k][9],  a2);
            a2 = fmaf(z2.z, lp[k][10], a2);
            a2 = fmaf(z2.w, lp[k][11], a2);
            a2 = fmaf(z3.x, lp[k][12], a2);
            a2 = fmaf(z3.y, lp[k][13], a2);
            a2 = fmaf(z3.z, lp[k][14], a2);
            a2 = fmaf(z3.w, lp[k][15], a2);

            mem[k] = a0r[k] + (a1 + a2);
        }
        xc = xn;
    }
}

extern "C" void kernel_launch(void* const* d_in, const int* in_sizes, int n_in,
                              void* d_out, int out_size)
{
    const float* x    = (const float*)d_in[0];
    const float* Win  = (const float*)d_in[1];
    const float* Wout = (const float*)d_in[2];
    const float* pin  = (const float*)d_in[3];
    const float* pout = (const float*)d_in[4];
    const float* l    = (const float*)d_in[5];
    float* y = (float*)d_out;

    rate_rnn_kernel<<<BATCH, NTHREADS>>>(x, Win, Wout, pin, pout, l, y);
}

// round 12
// speedup vs baseline: 1.0955x; 1.0252x over previous
#include <cuda_runtime.h>

// rate_RNN_mante: T=1000, B=64, I=4, H=1024, O=2, P=16
// Low-rank recurrence: r @ Wr^T = (r @ pout) @ (l*pin)^T
// One persistent CTA per batch element; mem state in registers.
// R12 = R5 core (scalar FMA, 2 barriers, smem zbuf broadcast)
//   + hoisted z-independent drive (R11)
//   + BOTH reductions trimmed to 4 dependent rounds: z partials written
//     2-per-index (32 cols), y partials 2-per-index (4 cols); phase 2
//     sums 16 partials each.

#define T_STEPS 1000
#define BATCH   64
#define I_DIM   4
#define H_DIM   1024
#define O_DIM   2
#define P_DIM   16
#define HPT     4                 // h-rows per thread
#define NTHREADS 256              // H_DIM / HPT
#define NWARPS  (NTHREADS / 32)
#define NRED    18                // 16 z-values + 2 y-values
#define PROW    36                // 32 z-partial cols + 4 y-partial cols

__device__ __forceinline__ float fast_tanh(float x) {
    float r;
    asm("tanh.approx.f32 %0, %1;" : "=f"(r) : "f"(x));
    return r;
}
__device__ __forceinline__ float shfl_xor_f(float v, int off) {
    return __shfl_xor_sync(0xffffffffu, v, off);
}

__global__ __launch_bounds__(NTHREADS, 1)
void rate_rnn_kernel(const float* __restrict__ x,     // (T,B,I,1)
                     const float* __restrict__ Win,   // (H,I)
                     const float* __restrict__ Wout,  // (O,H)
                     const float* __restrict__ pin,   // (H,P)
                     const float* __restrict__ pout,  // (H,P)
                     const float* __restrict__ l,     // (P,)
                     float* __restrict__ y)           // (T,B,O,1)
{
    const int b    = blockIdx.x;
    const int tid  = threadIdx.x;
    const int lane = tid & 31;
    const int warp = tid >> 5;

    __shared__ __align__(16) float pbuf[NWARPS][PROW];  // per-warp partials
    __shared__ __align__(16) float zbuf[P_DIM];         // broadcast z

    const float lm = 0.95122942450071400910f;  // exp(-DT/TAUM) = exp(-0.05)
    const float om = 1.0f - lm;

    // butterfly lane roles
    const bool hi16 = (lane & 16) != 0;
    const bool hi8  = (lane & 8)  != 0;
    const bool hi4  = (lane & 4)  != 0;
    const bool hi2  = (lane & 2)  != 0;
    const bool wyp  = (lane & 15) < 2;            // y-partial writer lanes 0,1,16,17
    const int  ycol = 32 + ((lane >> 4) << 1) + (lane & 1);  // y-partial column

    float lvec[P_DIM];
    #pragma unroll
    for (int p = 0; p < P_DIM; p++) lvec[p] = l[p];

    float mem[HPT];
    float win[HPT][I_DIM];     // om * Win (folded)
    float m[HPT][NRED];        // [pout (16) | Wout^T (2)]
    float lp[HPT][P_DIM];      // om * l * pin (folded)

    #pragma unroll
    for (int k = 0; k < HPT; k++) {
        const int h = tid + k * NTHREADS;
        mem[k] = 0.0f;
        #pragma unroll
        for (int i = 0; i < I_DIM; i++) win[k][i] = om * Win[h * I_DIM + i];
        #pragma unroll
        for (int p = 0; p < P_DIM; p++) {
            m[k][p]  = pout[h * P_DIM + p];
            lp[k][p] = om * lvec[p] * pin[h * P_DIM + p];
        }
        m[k][16] = Wout[h];           // Wout[0][h]
        m[k][17] = Wout[H_DIM + h];   // Wout[1][h]
    }

    const float4* xp = reinterpret_cast<const float4*>(x) + b;
    float4 xc = __ldg(xp);   // t = 0
    float4 xn = xc;

    // Iteration t: r_t = tanh(mem_t); y[t-1] = Wout.r_t; advance mem (t < T).
    for (int t = 0; t <= T_STEPS; t++) {
        {   // clamped prefetch of next x
            int tn = t + 1; if (tn > T_STEPS - 1) tn = T_STEPS - 1;
            xn = __ldg(xp + tn * BATCH);
        }

        // ---- phase 1: tanh + local accumulation ----
        float part[NRED];
        #pragma unroll
        for (int j = 0; j < NRED; j++) part[j] = 0.0f;

        #pragma unroll
        for (int k = 0; k < HPT; k++) {
            const float r = fast_tanh(mem[k]);
            #pragma unroll
            for (int j = 0; j < NRED; j++)
                part[j] = fmaf(r, m[k][j], part[j]);
        }

        // ---- z-independent drive, hoisted off the post-bar2 chain ----
        float a0r[HPT];
        #pragma unroll
        for (int k = 0; k < HPT; k++) {
            float a = lm * mem[k];
            a = fmaf(win[k][0], xc.x, a);
            a = fmaf(win[k][1], xc.y, a);
            a = fmaf(win[k][2], xc.z, a);
            a = fmaf(win[k][3], xc.w, a);
            a0r[k] = a;
        }

        // ---- split-butterfly z: rounds 16/8/4/2 (4 deep, no final xor-1) ----
        float v8[8];
        #pragma unroll
        for (int i = 0; i < 8; i++) {
            float send = hi16 ? part[i] : part[i + 8];
            float keep = hi16 ? part[i + 8] : part[i];
            v8[i] = keep + shfl_xor_f(send, 16);
        }
        float v4[4];
        #pragma unroll
        for (int i = 0; i < 4; i++) {
            float send = hi8 ? v8[i] : v8[i + 4];
            float keep = hi8 ? v8[i + 4] : v8[i];
            v4[i] = keep + shfl_xor_f(send, 8);
        }
        float v2[2];
        #pragma unroll
        for (int i = 0; i < 2; i++) {
            float send = hi4 ? v4[i] : v4[i + 2];
            float keep = hi4 ? v4[i + 2] : v4[i];
            v2[i] = keep + shfl_xor_f(send, 4);
        }
        float v1;
        {
            float send = hi2 ? v2[0] : v2[1];
            float keep = hi2 ? v2[1] : v2[0];
            v1 = keep + shfl_xor_f(send, 2);
        }
        // lanes 2j,2j+1 hold the two partials of z[j]

        // ---- y: split + rounds 8/4/2 (4 deep, no final xor-1) ----
        float wv;
        {
            float send = hi16 ? part[16] : part[17];
            float keep = hi16 ? part[17] : part[16];
            wv = keep + shfl_xor_f(send, 16);
        }
        wv += shfl_xor_f(wv, 8);
        wv += shfl_xor_f(wv, 4);
        wv += shfl_xor_f(wv, 2);
        // lane L holds mod-2-class partial of y[16+(L>>4)]

        pbuf[warp][lane] = v1;            // 32 z-partial cols, coalesced
        if (wyp) pbuf[warp][ycol] = wv;   // lanes 0,1,16,17 -> cols 32..35
        __syncthreads();

        // ---- phase 2: sum 16 partials per value (8 float2 loads + tree) ----
        if (tid < NRED) {
            const int c = (tid < P_DIM) ? (2 * tid) : (32 + 2 * (tid - P_DIM));
            float2 q0 = *reinterpret_cast<const float2*>(&pbuf[0][c]);
            float2 q1 = *reinterpret_cast<const float2*>(&pbuf[1][c]);
            float2 q2 = *reinterpret_cast<const float2*>(&pbuf[2][c]);
            float2 q3 = *reinterpret_cast<const float2*>(&pbuf[3][c]);
            float2 q4 = *reinterpret_cast<const float2*>(&pbuf[4][c]);
            float2 q5 = *reinterpret_cast<const float2*>(&pbuf[5][c]);
            float2 q6 = *reinterpret_cast<const float2*>(&pbuf[6][c]);
            float2 q7 = *reinterpret_cast<const float2*>(&pbuf[7][c]);
            float sx = ((q0.x + q1.x) + (q2.x + q3.x)) + ((q4.x + q5.x) + (q6.x + q7.x));
            float sy = ((q0.y + q1.y) + (q2.y + q3.y)) + ((q4.y + q5.y) + (q6.y + q7.y));
            float s  = sx + sy;
            if (tid < P_DIM) {
                zbuf[tid] = s;
            } else if (t > 0) {
                y[((t - 1) * BATCH + b) * O_DIM + (tid - P_DIM)] = s;
            }
        }
        __syncthreads();

        if (t == T_STEPS) break;

        // ---- phase 3: z feedback only (drive already in a0r) ----
        const float4* zv = reinterpret_cast<const float4*>(zbuf);
        const float4 z0 = zv[0], z1 = zv[1], z2 = zv[2], z3 = zv[3];

        #pragma unroll
        for (int k = 0; k < HPT; k++) {
            float a1 = z0.x * lp[k][0];
            a1 = fmaf(z0.y, lp[k][1],  a1);
            a1 = fmaf(z0.z, lp[k][2],  a1);
            a1 = fmaf(z0.w, lp[k][3],  a1);
            a1 = fmaf(z1.x, lp[k][4],  a1);
            a1 = fmaf(z1.y, lp[k][5],  a1);
            a1 = fmaf(z1.z, lp[k][6],  a1);
            a1 = fmaf(z1.w, lp[k][7],  a1);

            float a2 = z2.x * lp[k][8];
            a2 = fmaf(z2.y, lp[k][9],  a2);
            a2 = fmaf(z2.z, lp[k][10], a2);
            a2 = fmaf(z2.w, lp[k][11], a2);
            a2 = fmaf(z3.x, lp[k][12], a2);
            a2 = fmaf(z3.y, lp[k][13], a2);
            a2 = fmaf(z3.z, lp[k][14], a2);
            a2 = fmaf(z3.w, lp[k][15], a2);

            mem[k] = a0r[k] + (a1 + a2);
        }
        xc = xn;
    }
}

extern "C" void kernel_launch(void* const* d_in, const int* in_sizes, int n_in,
                              void* d_out, int out_size)
{
    const float* x    = (const float*)d_in[0];
    const float* Win  = (const float*)d_in[1];
    const float* Wout = (const float*)d_in[2];
    const float* pin  = (const float*)d_in[3];
    const float* pout = (const float*)d_in[4];
    const float* l    = (const float*)d_in[5];
    float* y = (float*)d_out;

    rate_rnn_kernel<<<BATCH, NTHREADS>>>(x, Win, Wout, pin, pout, l, y);
}